// round 10
// baseline (speedup 1.0000x reference)
#include <cuda_runtime.h>
#include <cstddef>

// Problem constants
#define Bx 8
#define Cc 64
#define Nn 512
#define Tt 288
#define Kk 32
#define TT 8            // t-tile per block
#define NTILE 16        // phase-B n-tile
#define YSTR 66         // sY c stride (floats)
#define CHN 8           // n's per chunk
#define NCH (Nn / CHN)  // 64 chunks
#define WCHF 512        // floats per warp-chunk: 8n * 8c * 8t
#define WRINGF (2 * WCHF)   // per-warp ring (2 bufs)

typedef unsigned long long u64;

// smem layout (floats)
#define OFF_HE   0                          // [512][32] HEs, k contiguous
#define OFF_EMT  (OFF_HE + Nn * Kk)         // [32][32]  edge_map transposed
#define OFF_UN   (OFF_EMT + Kk * Kk)        // union: per-warp x rings (8*1024) / y tile (8448)
#define UN_FLOATS 8448
#define SMEM_FLOATS (OFF_UN + UN_FLOATS)    // 25856 floats = 103424 B -> 2 CTAs/SM

// ---- packed f32x2 helpers (FFMA2 is PTX-only on sm_103a) ----
__device__ __forceinline__ u64 pack2(float x, float y) {
    u64 r; asm("mov.b64 %0, {%1, %2};" : "=l"(r) : "f"(x), "f"(y)); return r;
}
__device__ __forceinline__ float2 unpack2(u64 v) {
    float2 r; asm("mov.b64 {%0, %1}, %2;" : "=f"(r.x), "=f"(r.y) : "l"(v)); return r;
}
__device__ __forceinline__ u64 ffma2(u64 a, u64 b, u64 c) {
    u64 d; asm("fma.rn.f32x2 %0, %1, %2, %3;" : "=l"(d) : "l"(a), "l"(b), "l"(c)); return d;
}
__device__ __forceinline__ unsigned smem_u32(const void* p) {
    unsigned a;
    asm("{ .reg .u64 t; cvta.to.shared.u64 t, %1; cvt.u32.u64 %0, t; }" : "=r"(a) : "l"(p));
    return a;
}
__device__ __forceinline__ void cp_async16(unsigned dst, const void* src) {
    asm volatile("cp.async.cg.shared.global [%0], [%1], 16;" :: "r"(dst), "l"(src) : "memory");
}

extern __shared__ float smem[];

// ============================================================================
// Fully fused; phase A is BARRIER-FREE (warp-private cp.async rings).
// Block = 256 threads; warp w owns c in {4w..4w+3} u {4w+32..}, all 8 t.
// lane -> (cg = lane>>3, t = lane&7); thread owns c = 4w+cg and c+32.
// grid = (36 t-tiles, 8 b) = 288 blocks; 2 CTAs/SM -> single wave.
// ============================================================================
__global__ void __launch_bounds__(256, 2)
fused_hgl(const float* __restrict__ x, const float* __restrict__ HEs,
          const float* __restrict__ em, float* __restrict__ out) {
    float* sHE  = smem + OFF_HE;
    float* sEMT = smem + OFF_EMT;
    float* sUN  = smem + OFF_UN;          // per-warp x rings (phase A) / y tile (phase B)

    const int tid   = threadIdx.x;
    const int ttile = blockIdx.x;
    const int b     = blockIdx.y;
    const int t0    = ttile * TT;
    const int w     = tid >> 5;
    const int lane  = tid & 31;
    const int cg    = lane >> 3;          // 0..3
    const int t     = lane & 7;           // 0..7
    const int cA    = 4 * w + cg;         // first-half c
    // second-half c = cA + 32

    float* ringW = sUN + w * WRINGF;
    const unsigned ringBase = smem_u32(ringW);

    // ---- warp-private chunk issue: 4 x 16B cp.async per thread ----
    // warp chunk layout: [n(8)][crow(8)][t(8)] floats; crow = (c&3 ... ) mapping:
    // crow 0..3 -> c = 4w+crow ; crow 4..7 -> c = 4w+(crow-4)+32
    auto issue_chunk = [&](int ch) {
        const unsigned bufB = ringBase + (unsigned)((ch & 1) * WCHF) * 4u;
        #pragma unroll
        for (int i = 0; i < 4; i++) {
            int j    = lane * 4 + i;          // 0..127
            int half = j & 1;                 // 16B half of the 32B t-row
            int crow = (j >> 1) & 7;
            int n    = j >> 4;                // 0..7
            int c    = 4 * w + (crow & 3) + ((crow >> 2) << 5);
            const float* g = x + ((size_t)(b * Cc + c) * Nn + (size_t)ch * CHN + n) * Tt
                               + t0 + half * 4;
            unsigned d = bufB + (unsigned)(n * 64 + crow * 8 + half * 4) * 4u;
            cp_async16(d, g);
        }
        asm volatile("cp.async.commit_group;" ::: "memory");
    };

    issue_chunk(0);
    issue_chunk(1);

    // ---- stage HEs + EM^T (block-wide, once) ----
    const float4* heg = (const float4*)HEs;
    float4* sheg = (float4*)sHE;
    #pragma unroll
    for (int i = 0; i < 16; i++)
        sheg[i * 256 + tid] = heg[i * 256 + tid];
    #pragma unroll
    for (int i = 0; i < 4; i++) {
        int flat = i * 256 + tid;             // flat = k'*32 + j
        int kp = flat >> 5, k = flat & 31;
        sEMT[k * Kk + kp] = em[flat];         // sEMT[j][k'] = EM[k'][j]
    }
    __syncthreads();                          // HE visible; rings are warp-private

    // =========================== Phase A: HF (no block barriers) ============
    u64 accA[16], accB[16];
    #pragma unroll
    for (int i = 0; i < 16; i++) { accA[i] = 0ull; accB[i] = 0ull; }

    #pragma unroll 1
    for (int ch = 0; ch < NCH; ch++) {
        if (ch + 2 <= NCH - 1) asm volatile("cp.async.wait_group 1;" ::: "memory");
        else                   asm volatile("cp.async.wait_group 0;" ::: "memory");
        __syncwarp();                          // all lanes' copies for chunk ch done

        const float* sX = ringW + (ch & 1) * WCHF;
        #pragma unroll
        for (int i = 0; i < CHN; i++) {
            float xa = sX[i * 64 + cg * 8 + t];
            float xb = sX[i * 64 + 32 + cg * 8 + t];
            u64 xap = pack2(xa, xa);
            u64 xbp = pack2(xb, xb);
            const ulonglong2* he = (const ulonglong2*)(sHE + (ch * CHN + i) * Kk);
            #pragma unroll
            for (int q = 0; q < 8; q++) {      // broadcast LDS.128 -> 4 FFMA2
                ulonglong2 hh = he[q];
                accA[2 * q]     = ffma2(hh.x, xap, accA[2 * q]);
                accA[2 * q + 1] = ffma2(hh.y, xap, accA[2 * q + 1]);
                accB[2 * q]     = ffma2(hh.x, xbp, accB[2 * q]);
                accB[2 * q + 1] = ffma2(hh.y, xbp, accB[2 * q + 1]);
            }
        }
        __syncwarp();                          // reads done before refill
        if (ch + 2 < NCH) issue_chunk(ch + 2);
    }

    // ---- edge-map mix + HO = relu(mix)+HF (per c, register-local) ----
    {
        u64 hm[16];
        #pragma unroll
        for (int i = 0; i < 16; i++) hm[i] = 0ull;
        #pragma unroll
        for (int k = 0; k < Kk; k++) {
            float2 a = unpack2(accA[k >> 1]);
            float hf = (k & 1) ? a.y : a.x;
            u64 hb = pack2(hf, hf);
            const ulonglong2* emr = (const ulonglong2*)(sEMT + k * Kk);
            #pragma unroll
            for (int q = 0; q < 8; q++) {
                ulonglong2 ee = emr[q];
                hm[2 * q]     = ffma2(ee.x, hb, hm[2 * q]);
                hm[2 * q + 1] = ffma2(ee.y, hb, hm[2 * q + 1]);
            }
        }
        #pragma unroll
        for (int kp = 0; kp < 16; kp++) {
            float2 m = unpack2(hm[kp]);
            float2 f = unpack2(accA[kp]);
            accA[kp] = pack2(fmaxf(m.x, 0.f) + f.x, fmaxf(m.y, 0.f) + f.y);
        }
    }
    {
        u64 hm[16];
        #pragma unroll
        for (int i = 0; i < 16; i++) hm[i] = 0ull;
        #pragma unroll
        for (int k = 0; k < Kk; k++) {
            float2 a = unpack2(accB[k >> 1]);
            float hf = (k & 1) ? a.y : a.x;
            u64 hb = pack2(hf, hf);
            const ulonglong2* emr = (const ulonglong2*)(sEMT + k * Kk);
            #pragma unroll
            for (int q = 0; q < 8; q++) {
                ulonglong2 ee = emr[q];
                hm[2 * q]     = ffma2(ee.x, hb, hm[2 * q]);
                hm[2 * q + 1] = ffma2(ee.y, hb, hm[2 * q + 1]);
            }
        }
        #pragma unroll
        for (int kp = 0; kp < 16; kp++) {
            float2 m = unpack2(hm[kp]);
            float2 f = unpack2(accB[kp]);
            accB[kp] = pack2(fmaxf(m.x, 0.f) + f.x, fmaxf(m.y, 0.f) + f.y);
        }
    }
    __syncthreads();   // all rings dead; sUN becomes y tile

    // =========================== Phase B ====================================
    float* sY = sUN;
    const int enl = tid >> 4;            // 0..15 local n (epilogue)
    const int et  = (tid >> 1) & 7;      // 0..7  t
    const int ech = tid & 1;             // c half
    const int cb  = ech * 32;
    const size_t cstride = (size_t)Nn * Tt;

    #pragma unroll 1
    for (int nt = 0; nt < Nn / NTILE; nt++) {
        const int n0 = nt * NTILE;

        // GEMM: y[n] = dot(HE[n,:], HO[:]) via k-pair FFMA2 + horizontal add
        #pragma unroll 4
        for (int i = 0; i < NTILE; i++) {
            const ulonglong2* he = (const ulonglong2*)(sHE + (n0 + i) * Kk);
            u64 ya = 0ull, yb = 0ull;
            #pragma unroll
            for (int q = 0; q < 8; q++) {
                ulonglong2 hh = he[q];
                ya = ffma2(hh.x, accA[2 * q], ya);
                ya = ffma2(hh.y, accA[2 * q + 1], ya);
                yb = ffma2(hh.x, accB[2 * q], yb);
                yb = ffma2(hh.y, accB[2 * q + 1], yb);
            }
            float2 a  = unpack2(ya);
            float2 bb = unpack2(yb);
            sY[(i * TT + t) * YSTR + cA]      = a.x + a.y;
            sY[(i * TT + t) * YSTR + cA + 32] = bb.x + bb.y;
        }
        __syncthreads();

        // epilogue: relu + residual + LN over c (2 threads per (n,t), shfl pair)
        const int n = n0 + enl;
        const float* yrow = sY + (enl * TT + et) * YSTR + cb;
        const size_t xbase = ((size_t)(b * Cc + cb) * Nn + n) * Tt + t0 + et;

        float z[32];
        float s1 = 0.f, s2 = 0.f;
        #pragma unroll
        for (int i = 0; i < 32; i++) {
            float zz = fmaxf(yrow[i], 0.f) + x[xbase + (size_t)i * cstride];
            z[i] = zz;
            s1 += zz;
            s2 += zz * zz;
        }
        s1 += __shfl_xor_sync(0xffffffffu, s1, 1);
        s2 += __shfl_xor_sync(0xffffffffu, s2, 1);
        float mu  = s1 * (1.f / 64.f);
        float var = fmaf(mu, -mu, s2 * (1.f / 64.f));
        float inv = rsqrtf(var + 1e-5f);
        #pragma unroll
        for (int i = 0; i < 32; i++)
            out[xbase + (size_t)i * cstride] = (z[i] - mu) * inv;
        __syncthreads();
    }
}

// ============================================================================
extern "C" void kernel_launch(void* const* d_in, const int* in_sizes, int n_in,
                              void* d_out, int out_size) {
    const float* x   = (const float*)d_in[0];
    const float* HEs = (const float*)d_in[1];
    const float* em  = (const float*)d_in[2];
    float* out = (float*)d_out;

    const int smem_bytes = SMEM_FLOATS * 4;   // 103424 -> 2 CTAs/SM
    cudaFuncSetAttribute(fused_hgl, cudaFuncAttributeMaxDynamicSharedMemorySize, smem_bytes);

    fused_hgl<<<dim3(Tt / TT, Bx), 256, smem_bytes>>>(x, HEs, em, out);
}

// round 13
// speedup vs baseline: 1.0701x; 1.0701x over previous
#include <cuda_runtime.h>
#include <cstddef>

// Problem constants
#define Bx 8
#define Cc 64
#define Nn 512
#define Tt 288
#define Kk 32
#define TT 8            // t-tile per block
#define NTILE 16        // phase-B n-tile
#define YSTR 66         // sY c stride (floats)
#define CHN 4           // n's per chunk
#define NCH (Nn / CHN)  // 128 chunks
#define NBUF 4          // ring depth -> 3-chunk lookahead
#define WCHF (CHN * 8 * 8)      // floats per warp-chunk: 4n * 8crow * 8t = 256
#define WRINGF (NBUF * WCHF)    // per-warp ring = 1024 floats (4KB)

typedef unsigned long long u64;

// smem layout (floats)
#define OFF_HE   0                          // [512][32] HEs, k contiguous
#define OFF_EMT  (OFF_HE + Nn * Kk)         // [32][32]  edge_map transposed
#define OFF_UN   (OFF_EMT + Kk * Kk)        // union: per-warp x rings (8*1024) / y tile (8448)
#define UN_FLOATS 8448
#define SMEM_FLOATS (OFF_UN + UN_FLOATS)    // 25856 floats = 103424 B -> 2 CTAs/SM

// ---- packed f32x2 helpers (FFMA2 is PTX-only on sm_103a) ----
__device__ __forceinline__ u64 pack2(float x, float y) {
    u64 r; asm("mov.b64 %0, {%1, %2};" : "=l"(r) : "f"(x), "f"(y)); return r;
}
__device__ __forceinline__ float2 unpack2(u64 v) {
    float2 r; asm("mov.b64 {%0, %1}, %2;" : "=f"(r.x), "=f"(r.y) : "l"(v)); return r;
}
__device__ __forceinline__ u64 ffma2(u64 a, u64 b, u64 c) {
    u64 d; asm("fma.rn.f32x2 %0, %1, %2, %3;" : "=l"(d) : "l"(a), "l"(b), "l"(c)); return d;
}
__device__ __forceinline__ unsigned smem_u32(const void* p) {
    unsigned a;
    asm("{ .reg .u64 t; cvta.to.shared.u64 t, %1; cvt.u32.u64 %0, t; }" : "=r"(a) : "l"(p));
    return a;
}
__device__ __forceinline__ void cp_async16(unsigned dst, const void* src) {
    asm volatile("cp.async.cg.shared.global [%0], [%1], 16;" :: "r"(dst), "l"(src) : "memory");
}

extern __shared__ float smem[];

// ============================================================================
// Fully fused; phase A barrier-free with a 4-deep warp-private cp.async ring
// (3-chunk lookahead covers DRAM latency); phase-B epilogue x prefetched into
// registers under the GEMM. Block = 256 thr; warp w owns c in {4w..4w+3} u
// {+32}, all 8 t. grid = (36, 8) = 288 blocks; 2 CTAs/SM -> single wave.
// ============================================================================
__global__ void __launch_bounds__(256, 2)
fused_hgl(const float* __restrict__ x, const float* __restrict__ HEs,
          const float* __restrict__ em, float* __restrict__ out) {
    float* sHE  = smem + OFF_HE;
    float* sEMT = smem + OFF_EMT;
    float* sUN  = smem + OFF_UN;          // per-warp x rings (phase A) / y tile (phase B)

    const int tid   = threadIdx.x;
    const int ttile = blockIdx.x;
    const int b     = blockIdx.y;
    const int t0    = ttile * TT;
    const int w     = tid >> 5;
    const int lane  = tid & 31;
    const int cg    = lane >> 3;          // 0..3
    const int t     = lane & 7;           // 0..7
    const int cA    = 4 * w + cg;         // first-half c; second = cA + 32

    float* ringW = sUN + w * WRINGF;
    const unsigned ringBase = smem_u32(ringW);

    // ---- warp-private chunk issue: 2 x 16B cp.async per lane ----
    // chunk layout: [n(4)][crow(8)][t(8)]; crow 0..3 -> c=4w+crow, 4..7 -> +32
    auto issue_chunk = [&](int ch) {
        const unsigned bufB = ringBase + (unsigned)((ch & (NBUF - 1)) * WCHF) * 4u;
        #pragma unroll
        for (int i = 0; i < 2; i++) {
            int j    = lane * 2 + i;          // 0..63
            int half = j & 1;                 // 16B half of the 32B t-row
            int crow = (j >> 1) & 7;
            int n    = j >> 4;                // 0..3
            int c    = 4 * w + (crow & 3) + ((crow >> 2) << 5);
            const float* g = x + ((size_t)(b * Cc + c) * Nn + (size_t)ch * CHN + n) * Tt
                               + t0 + half * 4;
            unsigned d = bufB + (unsigned)(n * 64 + crow * 8 + half * 4) * 4u;
            cp_async16(d, g);
        }
        asm volatile("cp.async.commit_group;" ::: "memory");
    };

    issue_chunk(0); issue_chunk(1); issue_chunk(2); issue_chunk(3);

    // ---- stage HEs + EM^T (block-wide, once) ----
    const float4* heg = (const float4*)HEs;
    float4* sheg = (float4*)sHE;
    #pragma unroll
    for (int i = 0; i < 16; i++)
        sheg[i * 256 + tid] = heg[i * 256 + tid];
    #pragma unroll
    for (int i = 0; i < 4; i++) {
        int flat = i * 256 + tid;             // flat = k'*32 + j
        int kp = flat >> 5, k = flat & 31;
        sEMT[k * Kk + kp] = em[flat];         // sEMT[j][k'] = EM[k'][j]
    }
    __syncthreads();                          // HE visible; rings are warp-private

    // =========================== Phase A: HF (no block barriers) ============
    u64 accA[16], accB[16];
    #pragma unroll
    for (int i = 0; i < 16; i++) { accA[i] = 0ull; accB[i] = 0ull; }

    #pragma unroll 1
    for (int ch = 0; ch < NCH; ch++) {
        if      (ch + 3 < NCH) asm volatile("cp.async.wait_group 3;" ::: "memory");
        else if (ch + 2 < NCH) asm volatile("cp.async.wait_group 2;" ::: "memory");
        else if (ch + 1 < NCH) asm volatile("cp.async.wait_group 1;" ::: "memory");
        else                   asm volatile("cp.async.wait_group 0;" ::: "memory");
        __syncwarp();                          // all lanes' copies for chunk ch done

        const float* sX = ringW + (ch & (NBUF - 1)) * WCHF;
        #pragma unroll
        for (int i = 0; i < CHN; i++) {
            float xa = sX[i * 64 + cg * 8 + t];
            float xb = sX[i * 64 + 32 + cg * 8 + t];
            u64 xap = pack2(xa, xa);
            u64 xbp = pack2(xb, xb);
            const ulonglong2* he = (const ulonglong2*)(sHE + (ch * CHN + i) * Kk);
            #pragma unroll
            for (int q = 0; q < 8; q++) {      // broadcast LDS.128 -> 4 FFMA2
                ulonglong2 hh = he[q];
                accA[2 * q]     = ffma2(hh.x, xap, accA[2 * q]);
                accA[2 * q + 1] = ffma2(hh.y, xap, accA[2 * q + 1]);
                accB[2 * q]     = ffma2(hh.x, xbp, accB[2 * q]);
                accB[2 * q + 1] = ffma2(hh.y, xbp, accB[2 * q + 1]);
            }
        }
        __syncwarp();                          // reads done before refill
        if (ch + NBUF < NCH) issue_chunk(ch + NBUF);
    }

    // ---- edge-map mix + HO = relu(mix)+HF (per c, register-local) ----
    {
        u64 hm[16];
        #pragma unroll
        for (int i = 0; i < 16; i++) hm[i] = 0ull;
        #pragma unroll
        for (int k = 0; k < Kk; k++) {
            float2 a = unpack2(accA[k >> 1]);
            float hf = (k & 1) ? a.y : a.x;
            u64 hb = pack2(hf, hf);
            const ulonglong2* emr = (const ulonglong2*)(sEMT + k * Kk);
            #pragma unroll
            for (int q = 0; q < 8; q++) {
                ulonglong2 ee = emr[q];
                hm[2 * q]     = ffma2(ee.x, hb, hm[2 * q]);
                hm[2 * q + 1] = ffma2(ee.y, hb, hm[2 * q + 1]);
            }
        }
        #pragma unroll
        for (int kp = 0; kp < 16; kp++) {
            float2 m = unpack2(hm[kp]);
            float2 f = unpack2(accA[kp]);
            accA[kp] = pack2(fmaxf(m.x, 0.f) + f.x, fmaxf(m.y, 0.f) + f.y);
        }
    }
    {
        u64 hm[16];
        #pragma unroll
        for (int i = 0; i < 16; i++) hm[i] = 0ull;
        #pragma unroll
        for (int k = 0; k < Kk; k++) {
            float2 a = unpack2(accB[k >> 1]);
            float hf = (k & 1) ? a.y : a.x;
            u64 hb = pack2(hf, hf);
            const ulonglong2* emr = (const ulonglong2*)(sEMT + k * Kk);
            #pragma unroll
            for (int q = 0; q < 8; q++) {
                ulonglong2 ee = emr[q];
                hm[2 * q]     = ffma2(ee.x, hb, hm[2 * q]);
                hm[2 * q + 1] = ffma2(ee.y, hb, hm[2 * q + 1]);
            }
        }
        #pragma unroll
        for (int kp = 0; kp < 16; kp++) {
            float2 m = unpack2(hm[kp]);
            float2 f = unpack2(accB[kp]);
            accB[kp] = pack2(fmaxf(m.x, 0.f) + f.x, fmaxf(m.y, 0.f) + f.y);
        }
    }
    __syncthreads();   // all rings dead; sUN becomes y tile

    // =========================== Phase B ====================================
    float* sY = sUN;
    const int enl = tid >> 4;            // 0..15 local n (epilogue)
    const int et  = (tid >> 1) & 7;      // 0..7  t
    const int ech = tid & 1;             // c half
    const int cb  = ech * 32;
    const size_t cstride = (size_t)Nn * Tt;

    #pragma unroll 1
    for (int nt = 0; nt < Nn / NTILE; nt++) {
        const int n0 = nt * NTILE;
        const int n  = n0 + enl;
        const size_t xbase = ((size_t)(b * Cc + cb) * Nn + n) * Tt + t0 + et;

        // ---- prefetch epilogue x into registers (hidden under the GEMM) ----
        float z[32];
        #pragma unroll
        for (int i = 0; i < 32; i++)
            z[i] = x[xbase + (size_t)i * cstride];

        // ---- GEMM: y[n] = dot(HE[n,:], HO[:]) via k-pair FFMA2 + h-add ----
        #pragma unroll 4
        for (int i = 0; i < NTILE; i++) {
            const ulonglong2* he = (const ulonglong2*)(sHE + (n0 + i) * Kk);
            u64 ya = 0ull, yb = 0ull;
            #pragma unroll
            for (int q = 0; q < 8; q++) {
                ulonglong2 hh = he[q];
                ya = ffma2(hh.x, accA[2 * q], ya);
                ya = ffma2(hh.y, accA[2 * q + 1], ya);
                yb = ffma2(hh.x, accB[2 * q], yb);
                yb = ffma2(hh.y, accB[2 * q + 1], yb);
            }
            float2 a  = unpack2(ya);
            float2 bb = unpack2(yb);
            sY[(i * TT + t) * YSTR + cA]      = a.x + a.y;
            sY[(i * TT + t) * YSTR + cA + 32] = bb.x + bb.y;
        }
        __syncthreads();

        // ---- epilogue: relu + residual + LN over c (x already in z) ----
        const float* yrow = sY + (enl * TT + et) * YSTR + cb;
        float s1 = 0.f, s2 = 0.f;
        #pragma unroll
        for (int i = 0; i < 32; i++) {
            float zz = fmaxf(yrow[i], 0.f) + z[i];
            z[i] = zz;
            s1 += zz;
            s2 += zz * zz;
        }
        s1 += __shfl_xor_sync(0xffffffffu, s1, 1);
        s2 += __shfl_xor_sync(0xffffffffu, s2, 1);
        float mu  = s1 * (1.f / 64.f);
        float var = fmaf(mu, -mu, s2 * (1.f / 64.f));
        float inv = rsqrtf(var + 1e-5f);
        #pragma unroll
        for (int i = 0; i < 32; i++)
            out[xbase + (size_t)i * cstride] = (z[i] - mu) * inv;
        __syncthreads();
    }
}

// ============================================================================
extern "C" void kernel_launch(void* const* d_in, const int* in_sizes, int n_in,
                              void* d_out, int out_size) {
    const float* x   = (const float*)d_in[0];
    const float* HEs = (const float*)d_in[1];
    const float* em  = (const float*)d_in[2];
    float* out = (float*)d_out;

    const int smem_bytes = SMEM_FLOATS * 4;   // 103424 -> 2 CTAs/SM
    cudaFuncSetAttribute(fused_hgl, cudaFuncAttributeMaxDynamicSharedMemorySize, smem_bytes);

    fused_hgl<<<dim3(Tt / TT, Bx), 256, smem_bytes>>>(x, HEs, em, out);
}

// round 15
// speedup vs baseline: 1.3162x; 1.2299x over previous
#include <cuda_runtime.h>
#include <cstddef>

// Problem constants
#define Bx 8
#define Cc 64
#define Nn 512
#define Tt 288
#define Kk 32
#define TT 8            // t-tile per block
#define NTILE 8         // phase-B n-tile (halved: x-stage tile fits smem)
#define YSTR 66         // sY c stride (floats)
#define CHN 4           // n's per phase-A chunk
#define NCH (Nn / CHN)  // 128 chunks
#define NBUF 4          // ring depth -> 3-chunk lookahead
#define WCHF (CHN * 8 * 8)      // floats per warp-chunk = 256
#define WRINGF (NBUF * WCHF)    // per-warp ring = 1024 floats (4KB)

typedef unsigned long long u64;

// smem layout (floats)
#define OFF_HE   0                          // [512][32] HEs, k contiguous
#define OFF_EMT  (OFF_HE + Nn * Kk)         // [32][32]  edge_map transposed
#define OFF_UN   (OFF_EMT + Kk * Kk)        // union: phase-A rings (8*1024) / phase-B sY+sXE
#define UN_FLOATS 8448                      // >= max(8192, 4224+4096)
#define SMEM_FLOATS (OFF_UN + UN_FLOATS)    // 25856 floats = 103424 B -> 2 CTAs/SM

// ---- packed f32x2 helpers (FFMA2 is PTX-only on sm_103a) ----
__device__ __forceinline__ u64 pack2(float x, float y) {
    u64 r; asm("mov.b64 %0, {%1, %2};" : "=l"(r) : "f"(x), "f"(y)); return r;
}
__device__ __forceinline__ float2 unpack2(u64 v) {
    float2 r; asm("mov.b64 {%0, %1}, %2;" : "=f"(r.x), "=f"(r.y) : "l"(v)); return r;
}
__device__ __forceinline__ u64 ffma2(u64 a, u64 b, u64 c) {
    u64 d; asm("fma.rn.f32x2 %0, %1, %2, %3;" : "=l"(d) : "l"(a), "l"(b), "l"(c)); return d;
}
__device__ __forceinline__ unsigned smem_u32(const void* p) {
    unsigned a;
    asm("{ .reg .u64 t; cvta.to.shared.u64 t, %1; cvt.u32.u64 %0, t; }" : "=r"(a) : "l"(p));
    return a;
}
__device__ __forceinline__ void cp_async16(unsigned dst, const void* src) {
    asm volatile("cp.async.cg.shared.global [%0], [%1], 16;" :: "r"(dst), "l"(src) : "memory");
}

extern __shared__ float smem[];

// ============================================================================
// Fully fused; phase A barrier-free (4-deep warp-private cp.async rings);
// phase B stages epilogue x via cp.async into smem (no z[32] register blob)
// so peak live regs stay under the 128 cap -> no local-memory spills.
// Block = 256 thr; warp w owns c in {4w..4w+3} u {+32}, all 8 t.
// grid = (36 t-tiles, 8 b) = 288 blocks; 2 CTAs/SM -> single wave.
// ============================================================================
__global__ void __launch_bounds__(256, 2)
fused_hgl(const float* __restrict__ x, const float* __restrict__ HEs,
          const float* __restrict__ em, float* __restrict__ out) {
    float* sHE  = smem + OFF_HE;
    float* sEMT = smem + OFF_EMT;
    float* sUN  = smem + OFF_UN;

    const int tid   = threadIdx.x;
    const int ttile = blockIdx.x;
    const int b     = blockIdx.y;
    const int t0    = ttile * TT;
    const int w     = tid >> 5;
    const int lane  = tid & 31;
    const int cg    = lane >> 3;          // 0..3
    const int t     = lane & 7;           // 0..7
    const int cA    = 4 * w + cg;         // first-half c; second = cA + 32

    float* ringW = sUN + w * WRINGF;
    const unsigned ringBase = smem_u32(ringW);

    // ---- phase-A warp-private chunk issue: 2 x 16B cp.async per lane ----
    auto issue_chunk = [&](int ch) {
        const unsigned bufB = ringBase + (unsigned)((ch & (NBUF - 1)) * WCHF) * 4u;
        #pragma unroll
        for (int i = 0; i < 2; i++) {
            int j    = lane * 2 + i;          // 0..63
            int half = j & 1;
            int crow = (j >> 1) & 7;
            int n    = j >> 4;                // 0..3
            int c    = 4 * w + (crow & 3) + ((crow >> 2) << 5);
            const float* g = x + ((size_t)(b * Cc + c) * Nn + (size_t)ch * CHN + n) * Tt
                               + t0 + half * 4;
            unsigned d = bufB + (unsigned)(n * 64 + crow * 8 + half * 4) * 4u;
            cp_async16(d, g);
        }
        asm volatile("cp.async.commit_group;" ::: "memory");
    };

    issue_chunk(0); issue_chunk(1); issue_chunk(2); issue_chunk(3);

    // ---- stage HEs + EM^T (block-wide, once) ----
    const float4* heg = (const float4*)HEs;
    float4* sheg = (float4*)sHE;
    #pragma unroll
    for (int i = 0; i < 16; i++)
        sheg[i * 256 + tid] = heg[i * 256 + tid];
    #pragma unroll
    for (int i = 0; i < 4; i++) {
        int flat = i * 256 + tid;             // flat = k'*32 + j
        int kp = flat >> 5, k = flat & 31;
        sEMT[k * Kk + kp] = em[flat];         // sEMT[j][k'] = EM[k'][j]
    }
    __syncthreads();

    // =========================== Phase A: HF (no block barriers) ============
    u64 accA[16], accB[16];
    #pragma unroll
    for (int i = 0; i < 16; i++) { accA[i] = 0ull; accB[i] = 0ull; }

    #pragma unroll 1
    for (int ch = 0; ch < NCH; ch++) {
        if      (ch + 3 < NCH) asm volatile("cp.async.wait_group 3;" ::: "memory");
        else if (ch + 2 < NCH) asm volatile("cp.async.wait_group 2;" ::: "memory");
        else if (ch + 1 < NCH) asm volatile("cp.async.wait_group 1;" ::: "memory");
        else                   asm volatile("cp.async.wait_group 0;" ::: "memory");
        __syncwarp();

        const float* sX = ringW + (ch & (NBUF - 1)) * WCHF;
        #pragma unroll
        for (int i = 0; i < CHN; i++) {
            float xa = sX[i * 64 + cg * 8 + t];
            float xb = sX[i * 64 + 32 + cg * 8 + t];
            u64 xap = pack2(xa, xa);
            u64 xbp = pack2(xb, xb);
            const ulonglong2* he = (const ulonglong2*)(sHE + (ch * CHN + i) * Kk);
            #pragma unroll
            for (int q = 0; q < 8; q++) {      // broadcast LDS.128 -> 4 FFMA2
                ulonglong2 hh = he[q];
                accA[2 * q]     = ffma2(hh.x, xap, accA[2 * q]);
                accA[2 * q + 1] = ffma2(hh.y, xap, accA[2 * q + 1]);
                accB[2 * q]     = ffma2(hh.x, xbp, accB[2 * q]);
                accB[2 * q + 1] = ffma2(hh.y, xbp, accB[2 * q + 1]);
            }
        }
        __syncwarp();
        if (ch + NBUF < NCH) issue_chunk(ch + NBUF);
    }

    // ---- edge-map mix + HO = relu(mix)+HF (per c, register-local) ----
    {
        u64 hm[16];
        #pragma unroll
        for (int i = 0; i < 16; i++) hm[i] = 0ull;
        #pragma unroll
        for (int k = 0; k < Kk; k++) {
            float2 a = unpack2(accA[k >> 1]);
            float hf = (k & 1) ? a.y : a.x;
            u64 hb = pack2(hf, hf);
            const ulonglong2* emr = (const ulonglong2*)(sEMT + k * Kk);
            #pragma unroll
            for (int q = 0; q < 8; q++) {
                ulonglong2 ee = emr[q];
                hm[2 * q]     = ffma2(ee.x, hb, hm[2 * q]);
                hm[2 * q + 1] = ffma2(ee.y, hb, hm[2 * q + 1]);
            }
        }
        #pragma unroll
        for (int kp = 0; kp < 16; kp++) {
            float2 m = unpack2(hm[kp]);
            float2 f = unpack2(accA[kp]);
            accA[kp] = pack2(fmaxf(m.x, 0.f) + f.x, fmaxf(m.y, 0.f) + f.y);
        }
    }
    {
        u64 hm[16];
        #pragma unroll
        for (int i = 0; i < 16; i++) hm[i] = 0ull;
        #pragma unroll
        for (int k = 0; k < Kk; k++) {
            float2 a = unpack2(accB[k >> 1]);
            float hf = (k & 1) ? a.y : a.x;
            u64 hb = pack2(hf, hf);
            const ulonglong2* emr = (const ulonglong2*)(sEMT + k * Kk);
            #pragma unroll
            for (int q = 0; q < 8; q++) {
                ulonglong2 ee = emr[q];
                hm[2 * q]     = ffma2(ee.x, hb, hm[2 * q]);
                hm[2 * q + 1] = ffma2(ee.y, hb, hm[2 * q + 1]);
            }
        }
        #pragma unroll
        for (int kp = 0; kp < 16; kp++) {
            float2 m = unpack2(hm[kp]);
            float2 f = unpack2(accB[kp]);
            accB[kp] = pack2(fmaxf(m.x, 0.f) + f.x, fmaxf(m.y, 0.f) + f.y);
        }
    }
    __syncthreads();   // all rings dead; sUN becomes sY + sXE

    // =========================== Phase B ====================================
    float* sY  = sUN;                                // [8n][8t][YSTR]
    float* sXE = sUN + NTILE * TT * YSTR;            // [8n][64c][8t] (4096 fl)
    const unsigned xeBase = smem_u32(sXE);

    // epilogue mapping: 4 threads per (n,t), 16 c each
    const int q4  = tid & 3;                         // c quarter
    const int et  = (tid >> 2) & 7;                  // t
    const int enl = tid >> 5;                        // n (= warp id)
    const int cb  = q4 * 16;
    const size_t cstride = (size_t)Nn * Tt;

    #pragma unroll 1
    for (int nt = 0; nt < Nn / NTILE; nt++) {
        const int n0 = nt * NTILE;

        // ---- stage epilogue x tile via cp.async (hidden under the GEMM) ----
        #pragma unroll
        for (int i = 0; i < 4; i++) {
            int j  = i * 256 + tid;                  // 0..1023 float4 units
            int tq = j & 1;
            int c  = (j >> 1) & 63;
            int n  = j >> 7;                         // 0..7
            const float* g = x + ((size_t)(b * Cc + c) * Nn + n0 + n) * Tt + t0 + tq * 4;
            cp_async16(xeBase + (unsigned)(n * 512 + c * 8 + tq * 4) * 4u, g);
        }
        asm volatile("cp.async.commit_group;" ::: "memory");

        // ---- GEMM: y[n] = dot(HE[n,:], HO[:]) via k-pair FFMA2 + h-add ----
        #pragma unroll
        for (int i = 0; i < NTILE; i++) {
            const ulonglong2* he = (const ulonglong2*)(sHE + (n0 + i) * Kk);
            u64 ya = 0ull, yb = 0ull;
            #pragma unroll
            for (int q = 0; q < 8; q++) {
                ulonglong2 hh = he[q];
                ya = ffma2(hh.x, accA[2 * q], ya);
                ya = ffma2(hh.y, accA[2 * q + 1], ya);
                yb = ffma2(hh.x, accB[2 * q], yb);
                yb = ffma2(hh.y, accB[2 * q + 1], yb);
            }
            float2 a  = unpack2(ya);
            float2 bb = unpack2(yb);
            sY[(i * TT + t) * YSTR + cA]      = a.x + a.y;
            sY[(i * TT + t) * YSTR + cA + 32] = bb.x + bb.y;
        }
        asm volatile("cp.async.wait_group 0;" ::: "memory");
        __syncthreads();

        // ---- epilogue: relu + residual + LN over c (z[16] per thread) ----
        const int n = n0 + enl;
        const float* yrow = sY + (enl * TT + et) * YSTR + cb;
        const float* xrow = sXE + enl * 512 + cb * 8 + et;

        float z[16];
        float s1 = 0.f, s2 = 0.f;
        #pragma unroll
        for (int i = 0; i < 16; i++) {
            float zz = fmaxf(yrow[i], 0.f) + xrow[i * 8];
            z[i] = zz;
            s1 += zz;
            s2 += zz * zz;
        }
        s1 += __shfl_xor_sync(0xffffffffu, s1, 1);
        s2 += __shfl_xor_sync(0xffffffffu, s2, 1);
        s1 += __shfl_xor_sync(0xffffffffu, s1, 2);
        s2 += __shfl_xor_sync(0xffffffffu, s2, 2);
        float mu  = s1 * (1.f / 64.f);
        float var = fmaf(mu, -mu, s2 * (1.f / 64.f));
        float inv = rsqrtf(var + 1e-5f);

        const size_t obase = ((size_t)(b * Cc + cb) * Nn + n) * Tt + t0 + et;
        #pragma unroll
        for (int i = 0; i < 16; i++)
            out[obase + (size_t)i * cstride] = (z[i] - mu) * inv;
        __syncthreads();                             // sY/sXE reads done before next tile
    }
}

// ============================================================================
extern "C" void kernel_launch(void* const* d_in, const int* in_sizes, int n_in,
                              void* d_out, int out_size) {
    const float* x   = (const float*)d_in[0];
    const float* HEs = (const float*)d_in[1];
    const float* em  = (const float*)d_in[2];
    float* out = (float*)d_out;

    const int smem_bytes = SMEM_FLOATS * 4;   // 103424 -> 2 CTAs/SM
    cudaFuncSetAttribute(fused_hgl, cudaFuncAttributeMaxDynamicSharedMemorySize, smem_bytes);

    fused_hgl<<<dim3(Tt / TT, Bx), 256, smem_bytes>>>(x, HEs, em, out);
}

// round 16
// speedup vs baseline: 1.3192x; 1.0023x over previous
#include <cuda_runtime.h>
#include <cstddef>

// Problem constants
#define Bx 8
#define Cc 64
#define Nn 512
#define Tt 288
#define Kk 32
#define TT 8            // t-tile per block
#define NTILE 8         // phase-B n-tile (halved: x-stage tile fits smem)
#define YSTR 66         // sY c stride (floats)
#define CHN 4           // n's per phase-A chunk
#define NCH (Nn / CHN)  // 128 chunks
#define NBUF 4          // ring depth -> 3-chunk lookahead
#define WCHF (CHN * 8 * 8)      // floats per warp-chunk = 256
#define WRINGF (NBUF * WCHF)    // per-warp ring = 1024 floats (4KB)

typedef unsigned long long u64;

// smem layout (floats)
#define OFF_HE   0                          // [512][32] HEs, k contiguous
#define OFF_EMT  (OFF_HE + Nn * Kk)         // [32][32]  edge_map transposed
#define OFF_UN   (OFF_EMT + Kk * Kk)        // union: phase-A rings (8*1024) / phase-B sY+sXE
#define UN_FLOATS 8448                      // >= max(8192, 4224+4096)
#define SMEM_FLOATS (OFF_UN + UN_FLOATS)    // 25856 floats = 103424 B -> 2 CTAs/SM

// ---- packed f32x2 helpers (FFMA2 is PTX-only on sm_103a) ----
__device__ __forceinline__ u64 pack2(float x, float y) {
    u64 r; asm("mov.b64 %0, {%1, %2};" : "=l"(r) : "f"(x), "f"(y)); return r;
}
__device__ __forceinline__ float2 unpack2(u64 v) {
    float2 r; asm("mov.b64 {%0, %1}, %2;" : "=f"(r.x), "=f"(r.y) : "l"(v)); return r;
}
__device__ __forceinline__ u64 ffma2(u64 a, u64 b, u64 c) {
    u64 d; asm("fma.rn.f32x2 %0, %1, %2, %3;" : "=l"(d) : "l"(a), "l"(b), "l"(c)); return d;
}
__device__ __forceinline__ unsigned smem_u32(const void* p) {
    unsigned a;
    asm("{ .reg .u64 t; cvta.to.shared.u64 t, %1; cvt.u32.u64 %0, t; }" : "=r"(a) : "l"(p));
    return a;
}
__device__ __forceinline__ void cp_async16(unsigned dst, const void* src) {
    asm volatile("cp.async.cg.shared.global [%0], [%1], 16;" :: "r"(dst), "l"(src) : "memory");
}

extern __shared__ float smem[];

// ============================================================================
// Fully fused; phase A barrier-free (4-deep warp-private cp.async rings);
// phase B stages epilogue x via cp.async into smem (no z[32] register blob)
// so peak live regs stay under the 128 cap -> no local-memory spills.
// Block = 256 thr; warp w owns c in {4w..4w+3} u {+32}, all 8 t.
// grid = (36 t-tiles, 8 b) = 288 blocks; 2 CTAs/SM -> single wave.
// ============================================================================
__global__ void __launch_bounds__(256, 2)
fused_hgl(const float* __restrict__ x, const float* __restrict__ HEs,
          const float* __restrict__ em, float* __restrict__ out) {
    float* sHE  = smem + OFF_HE;
    float* sEMT = smem + OFF_EMT;
    float* sUN  = smem + OFF_UN;

    const int tid   = threadIdx.x;
    const int ttile = blockIdx.x;
    const int b     = blockIdx.y;
    const int t0    = ttile * TT;
    const int w     = tid >> 5;
    const int lane  = tid & 31;
    const int cg    = lane >> 3;          // 0..3
    const int t     = lane & 7;           // 0..7
    const int cA    = 4 * w + cg;         // first-half c; second = cA + 32

    float* ringW = sUN + w * WRINGF;
    const unsigned ringBase = smem_u32(ringW);

    // ---- phase-A warp-private chunk issue: 2 x 16B cp.async per lane ----
    auto issue_chunk = [&](int ch) {
        const unsigned bufB = ringBase + (unsigned)((ch & (NBUF - 1)) * WCHF) * 4u;
        #pragma unroll
        for (int i = 0; i < 2; i++) {
            int j    = lane * 2 + i;          // 0..63
            int half = j & 1;
            int crow = (j >> 1) & 7;
            int n    = j >> 4;                // 0..3
            int c    = 4 * w + (crow & 3) + ((crow >> 2) << 5);
            const float* g = x + ((size_t)(b * Cc + c) * Nn + (size_t)ch * CHN + n) * Tt
                               + t0 + half * 4;
            unsigned d = bufB + (unsigned)(n * 64 + crow * 8 + half * 4) * 4u;
            cp_async16(d, g);
        }
        asm volatile("cp.async.commit_group;" ::: "memory");
    };

    issue_chunk(0); issue_chunk(1); issue_chunk(2); issue_chunk(3);

    // ---- stage HEs + EM^T (block-wide, once) ----
    const float4* heg = (const float4*)HEs;
    float4* sheg = (float4*)sHE;
    #pragma unroll
    for (int i = 0; i < 16; i++)
        sheg[i * 256 + tid] = heg[i * 256 + tid];
    #pragma unroll
    for (int i = 0; i < 4; i++) {
        int flat = i * 256 + tid;             // flat = k'*32 + j
        int kp = flat >> 5, k = flat & 31;
        sEMT[k * Kk + kp] = em[flat];         // sEMT[j][k'] = EM[k'][j]
    }
    __syncthreads();

    // =========================== Phase A: HF (no block barriers) ============
    u64 accA[16], accB[16];
    #pragma unroll
    for (int i = 0; i < 16; i++) { accA[i] = 0ull; accB[i] = 0ull; }

    #pragma unroll 1
    for (int ch = 0; ch < NCH; ch++) {
        if      (ch + 3 < NCH) asm volatile("cp.async.wait_group 3;" ::: "memory");
        else if (ch + 2 < NCH) asm volatile("cp.async.wait_group 2;" ::: "memory");
        else if (ch + 1 < NCH) asm volatile("cp.async.wait_group 1;" ::: "memory");
        else                   asm volatile("cp.async.wait_group 0;" ::: "memory");
        __syncwarp();

        const float* sX = ringW + (ch & (NBUF - 1)) * WCHF;
        #pragma unroll
        for (int i = 0; i < CHN; i++) {
            float xa = sX[i * 64 + cg * 8 + t];
            float xb = sX[i * 64 + 32 + cg * 8 + t];
            u64 xap = pack2(xa, xa);
            u64 xbp = pack2(xb, xb);
            const ulonglong2* he = (const ulonglong2*)(sHE + (ch * CHN + i) * Kk);
            #pragma unroll
            for (int q = 0; q < 8; q++) {      // broadcast LDS.128 -> 4 FFMA2
                ulonglong2 hh = he[q];
                accA[2 * q]     = ffma2(hh.x, xap, accA[2 * q]);
                accA[2 * q + 1] = ffma2(hh.y, xap, accA[2 * q + 1]);
                accB[2 * q]     = ffma2(hh.x, xbp, accB[2 * q]);
                accB[2 * q + 1] = ffma2(hh.y, xbp, accB[2 * q + 1]);
            }
        }
        __syncwarp();
        if (ch + NBUF < NCH) issue_chunk(ch + NBUF);
    }

    // ---- edge-map mix + HO = relu(mix)+HF (per c, register-local) ----
    {
        u64 hm[16];
        #pragma unroll
        for (int i = 0; i < 16; i++) hm[i] = 0ull;
        #pragma unroll
        for (int k = 0; k < Kk; k++) {
            float2 a = unpack2(accA[k >> 1]);
            float hf = (k & 1) ? a.y : a.x;
            u64 hb = pack2(hf, hf);
            const ulonglong2* emr = (const ulonglong2*)(sEMT + k * Kk);
            #pragma unroll
            for (int q = 0; q < 8; q++) {
                ulonglong2 ee = emr[q];
                hm[2 * q]     = ffma2(ee.x, hb, hm[2 * q]);
                hm[2 * q + 1] = ffma2(ee.y, hb, hm[2 * q + 1]);
            }
        }
        #pragma unroll
        for (int kp = 0; kp < 16; kp++) {
            float2 m = unpack2(hm[kp]);
            float2 f = unpack2(accA[kp]);
            accA[kp] = pack2(fmaxf(m.x, 0.f) + f.x, fmaxf(m.y, 0.f) + f.y);
        }
    }
    {
        u64 hm[16];
        #pragma unroll
        for (int i = 0; i < 16; i++) hm[i] = 0ull;
        #pragma unroll
        for (int k = 0; k < Kk; k++) {
            float2 a = unpack2(accB[k >> 1]);
            float hf = (k & 1) ? a.y : a.x;
            u64 hb = pack2(hf, hf);
            const ulonglong2* emr = (const ulonglong2*)(sEMT + k * Kk);
            #pragma unroll
            for (int q = 0; q < 8; q++) {
                ulonglong2 ee = emr[q];
                hm[2 * q]     = ffma2(ee.x, hb, hm[2 * q]);
                hm[2 * q + 1] = ffma2(ee.y, hb, hm[2 * q + 1]);
            }
        }
        #pragma unroll
        for (int kp = 0; kp < 16; kp++) {
            float2 m = unpack2(hm[kp]);
            float2 f = unpack2(accB[kp]);
            accB[kp] = pack2(fmaxf(m.x, 0.f) + f.x, fmaxf(m.y, 0.f) + f.y);
        }
    }
    __syncthreads();   // all rings dead; sUN becomes sY + sXE

    // =========================== Phase B ====================================
    float* sY  = sUN;                                // [8n][8t][YSTR]
    float* sXE = sUN + NTILE * TT * YSTR;            // [8n][64c][8t] (4096 fl)
    const unsigned xeBase = smem_u32(sXE);

    // epilogue mapping: 4 threads per (n,t), 16 c each
    const int q4  = tid & 3;                         // c quarter
    const int et  = (tid >> 2) & 7;                  // t
    const int enl = tid >> 5;                        // n (= warp id)
    const int cb  = q4 * 16;
    const size_t cstride = (size_t)Nn * Tt;

    #pragma unroll 1
    for (int nt = 0; nt < Nn / NTILE; nt++) {
        const int n0 = nt * NTILE;

        // ---- stage epilogue x tile via cp.async (hidden under the GEMM) ----
        #pragma unroll
        for (int i = 0; i < 4; i++) {
            int j  = i * 256 + tid;                  // 0..1023 float4 units
            int tq = j & 1;
            int c  = (j >> 1) & 63;
            int n  = j >> 7;                         // 0..7
            const float* g = x + ((size_t)(b * Cc + c) * Nn + n0 + n) * Tt + t0 + tq * 4;
            cp_async16(xeBase + (unsigned)(n * 512 + c * 8 + tq * 4) * 4u, g);
        }
        asm volatile("cp.async.commit_group;" ::: "memory");

        // ---- GEMM: y[n] = dot(HE[n,:], HO[:]) via k-pair FFMA2 + h-add ----
        #pragma unroll
        for (int i = 0; i < NTILE; i++) {
            const ulonglong2* he = (const ulonglong2*)(sHE + (n0 + i) * Kk);
            u64 ya = 0ull, yb = 0ull;
            #pragma unroll
            for (int q = 0; q < 8; q++) {
                ulonglong2 hh = he[q];
                ya = ffma2(hh.x, accA[2 * q], ya);
                ya = ffma2(hh.y, accA[2 * q + 1], ya);
                yb = ffma2(hh.x, accB[2 * q], yb);
                yb = ffma2(hh.y, accB[2 * q + 1], yb);
            }
            float2 a  = unpack2(ya);
            float2 bb = unpack2(yb);
            sY[(i * TT + t) * YSTR + cA]      = a.x + a.y;
            sY[(i * TT + t) * YSTR + cA + 32] = bb.x + bb.y;
        }
        asm volatile("cp.async.wait_group 0;" ::: "memory");
        __syncthreads();

        // ---- epilogue: relu + residual + LN over c (z[16] per thread) ----
        const int n = n0 + enl;
        const float* yrow = sY + (enl * TT + et) * YSTR + cb;
        const float* xrow = sXE + enl * 512 + cb * 8 + et;

        float z[16];
        float s1 = 0.f, s2 = 0.f;
        #pragma unroll
        for (int i = 0; i < 16; i++) {
            float zz = fmaxf(yrow[i], 0.f) + xrow[i * 8];
            z[i] = zz;
            s1 += zz;
            s2 += zz * zz;
        }
        s1 += __shfl_xor_sync(0xffffffffu, s1, 1);
        s2 += __shfl_xor_sync(0xffffffffu, s2, 1);
        s1 += __shfl_xor_sync(0xffffffffu, s1, 2);
        s2 += __shfl_xor_sync(0xffffffffu, s2, 2);
        float mu  = s1 * (1.f / 64.f);
        float var = fmaf(mu, -mu, s2 * (1.f / 64.f));
        float inv = rsqrtf(var + 1e-5f);

        const size_t obase = ((size_t)(b * Cc + cb) * Nn + n) * Tt + t0 + et;
        #pragma unroll
        for (int i = 0; i < 16; i++)
            out[obase + (size_t)i * cstride] = (z[i] - mu) * inv;
        __syncthreads();                             // sY/sXE reads done before next tile
    }
}

// ============================================================================
extern "C" void kernel_launch(void* const* d_in, const int* in_sizes, int n_in,
                              void* d_out, int out_size) {
    const float* x   = (const float*)d_in[0];
    const float* HEs = (const float*)d_in[1];
    const float* em  = (const float*)d_in[2];
    float* out = (float*)d_out;

    const int smem_bytes = SMEM_FLOATS * 4;   // 103424 -> 2 CTAs/SM
    cudaFuncSetAttribute(fused_hgl, cudaFuncAttributeMaxDynamicSharedMemorySize, smem_bytes);

    fused_hgl<<<dim3(Tt / TT, Bx), 256, smem_bytes>>>(x, HEs, em, out);
}